// round 7
// baseline (speedup 1.0000x reference)
#include <cuda_runtime.h>
#include <cstdint>
#include <math.h>

#define SDIM 256
#define ADIM 128
#define HDIM 64
#define KKER 10
#define TB   128
#define NT   256

#define XS_O  0u
#define H_O   32768u
#define WT_O  40960u
#define WT_CH 2048u
#define XA_O  45056u
#define XA_CH 4096u
#define W3_O  53248u
#define B_O   53760u
#define OB_O  53888u
#define SMEMF 54912u   // *4 = 219648 B

__device__ __forceinline__ uint32_t tf32b(float x) {
    uint32_t u; asm("cvt.rna.tf32.f32 %0, %1;" : "=r"(u) : "f"(x)); return u;
}
__device__ __forceinline__ float tf32f(float x) { return __uint_as_float(tf32b(x)); }
__device__ __forceinline__ float sigf(float x) { return 1.0f / (1.0f + __expf(-x)); }

__device__ __forceinline__ void mma8(float c[4], float a0, float a1, float a2, float a3,
                                     float b0, float b1) {
    asm volatile("mma.sync.aligned.m16n8k8.row.col.f32.tf32.tf32.f32 "
                 "{%0,%1,%2,%3}, {%4,%5,%6,%7}, {%8,%9}, {%0,%1,%2,%3};"
                 : "+f"(c[0]), "+f"(c[1]), "+f"(c[2]), "+f"(c[3])
                 : "r"(__float_as_uint(a0)), "r"(__float_as_uint(a1)),
                   "r"(__float_as_uint(a2)), "r"(__float_as_uint(a3)),
                   "r"(__float_as_uint(b0)), "r"(__float_as_uint(b1)));
}

// interleaved-pair layout: element c in an 8-group sits at ((c&3)<<1)|((c>>2)&1)
__device__ __forceinline__ void stage_w(const float* __restrict__ g, int IN, int c0,
                                        float* __restrict__ dst, int tid) {
    #pragma unroll
    for (int jj = 0; jj < 2; jj++) {
        int idx = tid + NT * jj, o = idx >> 3, j = idx & 7;
        float4 v = *reinterpret_cast<const float4*>(g + o * IN + c0 + (j << 2));
        float* d = dst + (((j >> 1) * 64 + o) << 3) + (j & 1);
        d[0] = tf32f(v.x); d[2] = tf32f(v.y); d[4] = tf32f(v.z); d[6] = tf32f(v.w);
    }
}
__device__ __forceinline__ void stage_xa(const float* __restrict__ act, int b0, int c0,
                                         float* __restrict__ dst, int tid) {
    #pragma unroll
    for (int jj = 0; jj < 4; jj++) {
        int idx = tid + NT * jj, r = idx >> 3, j = idx & 7;
        float4 v = *reinterpret_cast<const float4*>(act + (size_t)(b0 + r) * ADIM + c0 + (j << 2));
        float* d = dst + (((j >> 1) * 128 + r) << 3) + (j & 1);
        d[0] = tf32f(v.x); d[2] = tf32f(v.y); d[4] = tf32f(v.z); d[6] = tf32f(v.w);
    }
}

// warp m32 x n32 over one 32-k chunk
__device__ __forceinline__ void mma_chunk(const float* __restrict__ A, int cg0,
                                          const float* __restrict__ wtb,
                                          float acc[2][4][4], int wbase, int nc0, int g, int t) {
    #pragma unroll
    for (int s = 0; s < 4; s++) {
        const float* ap = A + (((cg0 + s) * 128 + wbase + g) << 3) + 2 * t;
        float2 a00 = *reinterpret_cast<const float2*>(ap);
        float2 a01 = *reinterpret_cast<const float2*>(ap + 64);
        float2 a10 = *reinterpret_cast<const float2*>(ap + 128);
        float2 a11 = *reinterpret_cast<const float2*>(ap + 192);
        #pragma unroll
        for (int nt = 0; nt < 4; nt++) {
            const float* bp = wtb + ((s * 64 + nc0 + nt * 8 + g) << 3) + 2 * t;
            float2 b = *reinterpret_cast<const float2*>(bp);
            mma8(acc[0][nt], a00.x, a01.x, a00.y, a01.y, b.x, b.y);
            mma8(acc[1][nt], a10.x, a11.x, a10.y, a11.y, b.x, b.y);
        }
    }
}
__device__ __forceinline__ void zacc(float acc[2][4][4]) {
    #pragma unroll
    for (int m = 0; m < 2; m++)
        #pragma unroll
        for (int n = 0; n < 4; n++)
            #pragma unroll
            for (int i = 0; i < 4; i++) acc[m][n][i] = 0.0f;
}
__device__ __forceinline__ void epi_h(const float acc[2][4][4], float* __restrict__ h,
                                      const float* __restrict__ bias,
                                      int wbase, int nc0, int g, int t) {
    int cc0 = 2 * t, cc1 = 2 * t + 1;
    int p0 = ((cc0 & 3) << 1) | ((cc0 >> 2) & 1);
    int p1 = ((cc1 & 3) << 1) | ((cc1 >> 2) & 1);
    #pragma unroll
    for (int mt = 0; mt < 2; mt++) {
        int r0 = wbase + 16 * mt + g;
        #pragma unroll
        for (int nt = 0; nt < 4; nt++) {
            int ng = (nc0 >> 3) + nt;
            float b0 = bias[ng * 8 + cc0], b1 = bias[ng * 8 + cc1];
            float* hp = h + ((ng * 128 + r0) << 3);
            hp[p0]      = tf32f(fmaxf(acc[mt][nt][0] + b0, 0.f));
            hp[p1]      = tf32f(fmaxf(acc[mt][nt][1] + b1, 0.f));
            hp[64 + p0] = tf32f(fmaxf(acc[mt][nt][2] + b0, 0.f));
            hp[64 + p1] = tf32f(fmaxf(acc[mt][nt][3] + b1, 0.f));
        }
    }
}

__global__ void __launch_bounds__(NT, 1)
qplex_mma3_kernel(
    const float* __restrict__ states, const float* __restrict__ actions,
    const float* __restrict__ kW1, const float* __restrict__ kb1,
    const float* __restrict__ kW2, const float* __restrict__ kb2,
    const float* __restrict__ kW3, const float* __restrict__ kb3,
    const float* __restrict__ aW1, const float* __restrict__ ab1,
    const float* __restrict__ aW2, const float* __restrict__ ab2,
    const float* __restrict__ aW3, const float* __restrict__ ab3,
    const float* __restrict__ cW1, const float* __restrict__ cb1,
    const float* __restrict__ cW2, const float* __restrict__ cb2,
    const float* __restrict__ cW3, const float* __restrict__ cb3,
    float* __restrict__ out)
{
    extern __shared__ float sm[];
    float* xs = sm + XS_O;   float* h = sm + H_O;    float* wt = sm + WT_O;
    float* xa = sm + XA_O;   float* w3t = sm + W3_O; float* bs = sm + B_O;
    float* ob = sm + OB_O;

    const int tid = threadIdx.x, lane = tid & 31;
    const int g = lane >> 2, t = lane & 3;
    const int wid = tid >> 5, rg = wid >> 1, nh = wid & 1;
    const int wbase = rg << 5, nc0 = nh << 5;
    const int b0 = blockIdx.x * TB;

    #pragma unroll 4
    for (int jj = 0; jj < 32; jj++) {
        int idx = tid + NT * jj, r = idx >> 6, c4 = idx & 63;
        float4 v = *reinterpret_cast<const float4*>(states + (size_t)(b0 + r) * SDIM + (c4 << 2));
        float* d = xs + (((c4 >> 1) * 128 + r) << 3) + (c4 & 1);
        d[0] = tf32f(v.x); d[2] = tf32f(v.y); d[4] = tf32f(v.z); d[6] = tf32f(v.w);
    }

    const float* W1s[3] = {kW1, aW1, cW1};
    const float* B1s[3] = {kb1, ab1, cb1};
    const float* W2s[3] = {kW2, aW2, cW2};
    const float* B2s[3] = {kb2, ab2, cb2};

    float acc[2][4][4], keyr = 0.f, agr[8], accr[8];
    #pragma unroll
    for (int o = 0; o < 8; o++) { accr[o] = 0.f; agr[o] = 0.f; }

    for (int k = 0; k < KKER; k++) {
        for (int net = 0; net < 3; net++) {
            const int IN = (net == 2) ? (SDIM + ADIM) : SDIM;
            const int NCH = IN >> 5;
            const float* W1k = W1s[net] + (size_t)k * HDIM * IN;

            __syncthreads();
            if (tid < 64) {
                bs[tid]      = __ldg(B1s[net] + k * HDIM + tid);
                bs[64 + tid] = __ldg(B2s[net] + k * HDIM + tid);
            }
            stage_w(W1k, IN, 0,  wt,         tid);
            stage_w(W1k, IN, 32, wt + WT_CH, tid);
            __syncthreads();

            // ---- layer 1 ----
            zacc(acc);
            for (int j = 0; j < NCH; j++) {
                if (j < 8) mma_chunk(xs, j << 2, wt + (j & 1) * WT_CH, acc, wbase, nc0, g, t);
                else       mma_chunk(xa + (j & 1) * XA_CH, 0, wt + (j & 1) * WT_CH, acc, wbase, nc0, g, t);
                __syncthreads();
                int jn = j + 2;
                if (jn < NCH) {
                    stage_w(W1k, IN, jn << 5, wt + (jn & 1) * WT_CH, tid);
                    if (jn >= 8) stage_xa(actions, b0, (jn - 8) << 5, xa + (jn & 1) * XA_CH, tid);
                }
            }
            epi_h(acc, h, bs, wbase, nc0, g, t);

            // ---- stage W2 + W3 ----
            const float* W2k = W2s[net] + (size_t)k * HDIM * HDIM;
            stage_w(W2k, HDIM, 0,  wt,         tid);
            stage_w(W2k, HDIM, 32, wt + WT_CH, tid);
            if (tid < 128) {
                int o = tid >> 4, c4 = tid & 15;
                float4 v;
                if (net == 0) {
                    const float* g3 = kW3 + (size_t)k * HDIM;
                    v = (o == 0) ? *reinterpret_cast<const float4*>(g3 + (c4 << 2))
                                 : make_float4(0.f, 0.f, 0.f, 0.f);
                } else {
                    const float* g3 = ((net == 1) ? aW3 : cW3) + (size_t)k * 8 * HDIM;
                    v = *reinterpret_cast<const float4*>(g3 + o * HDIM + (c4 << 2));
                }
                float* d = w3t + (((c4 >> 1) * 8 + o) << 3) + (c4 & 1);
                d[0] = tf32f(v.x); d[2] = tf32f(v.y); d[4] = tf32f(v.z); d[6] = tf32f(v.w);
            }
            __syncthreads();

            // ---- layer 2 ----
            zacc(acc);
            mma_chunk(h, 0, wt,         acc, wbase, nc0, g, t);
            mma_chunk(h, 4, wt + WT_CH, acc, wbase, nc0, g, t);
            __syncthreads();
            epi_h(acc, h, bs + 64, wbase, nc0, g, t);
            __syncthreads();

            // ---- layer 3 (m32 x n8, nh==0 warps) ----
            if (nh == 0) {
                float a3[2][4];
                #pragma unroll
                for (int m = 0; m < 2; m++)
                    #pragma unroll
                    for (int i = 0; i < 4; i++) a3[m][i] = 0.f;
                #pragma unroll
                for (int s = 0; s < 8; s++) {
                    const float* ap = h + ((s * 128 + wbase + g) << 3) + 2 * t;
                    float2 a00 = *reinterpret_cast<const float2*>(ap);
                    float2 a01 = *reinterpret_cast<const float2*>(ap + 64);
                    float2 a10 = *reinterpret_cast<const float2*>(ap + 128);
                    float2 a11 = *reinterpret_cast<const float2*>(ap + 192);
                    const float* bp = w3t + ((s * 8 + g) << 3) + 2 * t;
                    float2 b = *reinterpret_cast<const float2*>(bp);
                    mma8(a3[0], a00.x, a01.x, a00.y, a01.y, b.x, b.y);
                    mma8(a3[1], a10.x, a11.x, a10.y, a11.y, b.x, b.y);
                }
                #pragma unroll
                for (int mt = 0; mt < 2; mt++) {
                    int r0 = wbase + 16 * mt + g;
                    *reinterpret_cast<float2*>(ob + r0 * 8 + 2 * t)       = make_float2(a3[mt][0], a3[mt][1]);
                    *reinterpret_cast<float2*>(ob + (r0 + 8) * 8 + 2 * t) = make_float2(a3[mt][2], a3[mt][3]);
                }
            }
            __syncthreads();
            if (tid < 128) {
                const float* orow = ob + tid * 8;
                if (net == 0) {
                    keyr = fabsf(orow[0] + __ldg(kb3 + k)) + 1e-10f;
                } else if (net == 1) {
                    #pragma unroll
                    for (int o = 0; o < 8; o++)
                        agr[o] = sigf(orow[o] + __ldg(ab3 + k * 8 + o));
                } else {
                    #pragma unroll
                    for (int o = 0; o < 8; o++)
                        accr[o] += keyr * agr[o] * sigf(orow[o] + __ldg(cb3 + k * 8 + o));
                }
            }
        }
    }

    if (tid < 128) {
        float4* op = reinterpret_cast<float4*>(out + (size_t)(b0 + tid) * 8);
        op[0] = make_float4(accr[0], accr[1], accr[2], accr[3]);
        op[1] = make_float4(accr[4], accr[5], accr[6], accr[7]);
    }
}

extern "C" void kernel_launch(void* const* d_in, const int* in_sizes, int n_in,
                              void* d_out, int out_size)
{
    const float* states  = (const float*)d_in[0];
    const float* actions = (const float*)d_in[1];
    const float* kW1 = (const float*)d_in[2];  const float* kb1 = (const float*)d_in[3];
    const float* kW2 = (const float*)d_in[4];  const float* kb2 = (const float*)d_in[5];
    const float* kW3 = (const float*)d_in[6];  const float* kb3 = (const float*)d_in[7];
    const float* aW1 = (const float*)d_in[8];  const float* ab1 = (const float*)d_in[9];
    const float* aW2 = (const float*)d_in[10]; const float* ab2 = (const float*)d_in[11];
    const float* aW3 = (const float*)d_in[12]; const float* ab3 = (const float*)d_in[13];
    const float* cW1 = (const float*)d_in[14]; const float* cb1 = (const float*)d_in[15];
    const float* cW2 = (const float*)d_in[16]; const float* cb2 = (const float*)d_in[17];
    const float* cW3 = (const float*)d_in[18]; const float* cb3 = (const float*)d_in[19];
    float* out = (float*)d_out;

    const size_t smem = SMEMF * sizeof(float);
    cudaFuncSetAttribute(qplex_mma3_kernel,
                         cudaFuncAttributeMaxDynamicSharedMemorySize, (int)smem);
    qplex_mma3_kernel<<<65536 / TB, NT, smem>>>(
        states, actions, kW1, kb1, kW2, kb2, kW3, kb3,
        aW1, ab1, aW2, ab2, aW3, ab3, cW1, cb1, cW2, cb2, cW3, cb3, out);
}

// round 8
// speedup vs baseline: 1.5727x; 1.5727x over previous
#include <cuda_runtime.h>
#include <cstdint>
#include <math.h>

#define SDIM 256
#define ADIM 128
#define HDIM 64
#define KKER 10
#define TB   64
#define NT   256
#define CGS  514      // padded cg stride (floats): conflict-free STS + LDS

#define XS_O  0u          // 32 cg
#define H_O   16448u      // 8 cg
#define WT_O  20560u      // 4 cg (single buffer)
#define XA_O  22616u      // 4 cg (single buffer)
#define W3_O  24672u      // 8 cg x 66
#define B_O   25200u
#define OB_O  25328u
#define SMEMF 25840u      // *4 = 103360 B -> 2 CTAs/SM

__device__ __forceinline__ uint32_t tf32b(float x) {
    uint32_t u; asm("cvt.rna.tf32.f32 %0, %1;" : "=r"(u) : "f"(x)); return u;
}
__device__ __forceinline__ float tf32f(float x) { return __uint_as_float(tf32b(x)); }
__device__ __forceinline__ float sigf(float x) { return 1.0f / (1.0f + __expf(-x)); }

__device__ __forceinline__ void mma8(float c[4], float a0, float a1, float a2, float a3,
                                     float b0, float b1) {
    asm volatile("mma.sync.aligned.m16n8k8.row.col.f32.tf32.tf32.f32 "
                 "{%0,%1,%2,%3}, {%4,%5,%6,%7}, {%8,%9}, {%0,%1,%2,%3};"
                 : "+f"(c[0]), "+f"(c[1]), "+f"(c[2]), "+f"(c[3])
                 : "r"(__float_as_uint(a0)), "r"(__float_as_uint(a1)),
                   "r"(__float_as_uint(a2)), "r"(__float_as_uint(a3)),
                   "r"(__float_as_uint(b0)), "r"(__float_as_uint(b1)));
}

// prefetch one [64 out x 32 k] weight chunk into regs (coalesced LDG.128)
__device__ __forceinline__ void pf_w(const float* __restrict__ g, int IN, int c0,
                                     int tid, float4& v0, float4& v1) {
    int i1 = tid + 256;
    v0 = __ldg(reinterpret_cast<const float4*>(g + (tid >> 3) * IN + c0 + ((tid & 7) << 2)));
    v1 = __ldg(reinterpret_cast<const float4*>(g + (i1 >> 3) * IN + c0 + ((i1 & 7) << 2)));
}
__device__ __forceinline__ void sts_w(float* __restrict__ wt, int tid, float4 v0, float4 v1) {
    {   int o = tid >> 3, j = tid & 7;
        float* d = wt + (j >> 1) * CGS + o * 8 + (j & 1);
        d[0] = tf32f(v0.x); d[2] = tf32f(v0.y); d[4] = tf32f(v0.z); d[6] = tf32f(v0.w); }
    {   int i1 = tid + 256, o = i1 >> 3, j = i1 & 7;
        float* d = wt + (j >> 1) * CGS + o * 8 + (j & 1);
        d[0] = tf32f(v1.x); d[2] = tf32f(v1.y); d[4] = tf32f(v1.z); d[6] = tf32f(v1.w); }
}
// prefetch/stage one [64 rows x 32 col] action chunk
__device__ __forceinline__ void pf_xa(const float* __restrict__ act, int b0, int c0,
                                      int tid, float4& v0, float4& v1) {
    int i1 = tid + 256;
    v0 = __ldg(reinterpret_cast<const float4*>(act + (size_t)(b0 + (tid >> 3)) * ADIM + c0 + ((tid & 7) << 2)));
    v1 = __ldg(reinterpret_cast<const float4*>(act + (size_t)(b0 + (i1 >> 3)) * ADIM + c0 + ((i1 & 7) << 2)));
}
__device__ __forceinline__ void sts_xa(float* __restrict__ xa, int tid, float4 v0, float4 v1) {
    {   int r = tid >> 3, j = tid & 7;
        float* d = xa + (j >> 1) * CGS + r * 8 + (j & 1);
        d[0] = tf32f(v0.x); d[2] = tf32f(v0.y); d[4] = tf32f(v0.z); d[6] = tf32f(v0.w); }
    {   int i1 = tid + 256, r = i1 >> 3, j = i1 & 7;
        float* d = xa + (j >> 1) * CGS + r * 8 + (j & 1);
        d[0] = tf32f(v1.x); d[2] = tf32f(v1.y); d[4] = tf32f(v1.z); d[6] = tf32f(v1.w); }
}

// warp m16 x n32 over one 32-k chunk
__device__ __forceinline__ void mma_chunk(const float* __restrict__ A, int cg0,
                                          const float* __restrict__ wtb,
                                          float acc[4][4], int wbase, int nc0, int g, int t) {
    #pragma unroll
    for (int s = 0; s < 4; s++) {
        const float* ap = A + (cg0 + s) * CGS + (wbase + g) * 8 + 2 * t;
        float2 fa = *reinterpret_cast<const float2*>(ap);
        float2 fb = *reinterpret_cast<const float2*>(ap + 64);
        #pragma unroll
        for (int nt = 0; nt < 4; nt++) {
            const float* bp = wtb + s * CGS + (nc0 + nt * 8 + g) * 8 + 2 * t;
            float2 b = *reinterpret_cast<const float2*>(bp);
            mma8(acc[nt], fa.x, fb.x, fa.y, fb.y, b.x, b.y);
        }
    }
}
__device__ __forceinline__ void zacc(float acc[4][4]) {
    #pragma unroll
    for (int n = 0; n < 4; n++)
        #pragma unroll
        for (int i = 0; i < 4; i++) acc[n][i] = 0.0f;
}
__device__ __forceinline__ void epi_h(const float acc[4][4], float* __restrict__ h,
                                      const float* __restrict__ bias,
                                      int wbase, int nc0, int g, int t) {
    int cc0 = 2 * t, cc1 = 2 * t + 1;
    int p0 = ((cc0 & 3) << 1) | ((cc0 >> 2) & 1);
    int p1 = ((cc1 & 3) << 1) | ((cc1 >> 2) & 1);
    #pragma unroll
    for (int nt = 0; nt < 4; nt++) {
        int ng = (nc0 >> 3) + nt;
        float b0 = bias[ng * 8 + cc0], b1 = bias[ng * 8 + cc1];
        float* hp = h + ng * CGS + (wbase + g) * 8;
        hp[p0]      = tf32f(fmaxf(acc[nt][0] + b0, 0.f));
        hp[p1]      = tf32f(fmaxf(acc[nt][1] + b1, 0.f));
        hp[64 + p0] = tf32f(fmaxf(acc[nt][2] + b0, 0.f));
        hp[64 + p1] = tf32f(fmaxf(acc[nt][3] + b1, 0.f));
    }
}

__global__ void __launch_bounds__(NT, 2)
qplex_mma4_kernel(
    const float* __restrict__ states, const float* __restrict__ actions,
    const float* __restrict__ kW1, const float* __restrict__ kb1,
    const float* __restrict__ kW2, const float* __restrict__ kb2,
    const float* __restrict__ kW3, const float* __restrict__ kb3,
    const float* __restrict__ aW1, const float* __restrict__ ab1,
    const float* __restrict__ aW2, const float* __restrict__ ab2,
    const float* __restrict__ aW3, const float* __restrict__ ab3,
    const float* __restrict__ cW1, const float* __restrict__ cb1,
    const float* __restrict__ cW2, const float* __restrict__ cb2,
    const float* __restrict__ cW3, const float* __restrict__ cb3,
    float* __restrict__ out)
{
    extern __shared__ float sm[];
    float* xs = sm + XS_O;   float* h = sm + H_O;    float* wt = sm + WT_O;
    float* xa = sm + XA_O;   float* w3t = sm + W3_O; float* bs = sm + B_O;
    float* ob = sm + OB_O;

    const int tid = threadIdx.x, lane = tid & 31;
    const int g = lane >> 2, t = lane & 3;
    const int wid = tid >> 5, rg = wid >> 1, nh = wid & 1;
    const int wbase = rg << 4, nc0 = nh << 5;
    const int b0 = blockIdx.x * TB;

    // stage states [64 x 256] -> xs (once); conflict-free STS
    #pragma unroll
    for (int jj = 0; jj < 16; jj++) {
        int idx = tid + NT * jj, r = idx >> 6, c4 = idx & 63;
        float4 v = *reinterpret_cast<const float4*>(states + (size_t)(b0 + r) * SDIM + (c4 << 2));
        float* d = xs + (c4 >> 1) * CGS + r * 8 + (c4 & 1);
        d[0] = tf32f(v.x); d[2] = tf32f(v.y); d[4] = tf32f(v.z); d[6] = tf32f(v.w);
    }
    __syncthreads();

    const float* W1s[3] = {kW1, aW1, cW1};
    const float* B1s[3] = {kb1, ab1, cb1};
    const float* W2s[3] = {kW2, aW2, cW2};
    const float* B2s[3] = {kb2, ab2, cb2};

    float acc[4][4], keyr = 0.f, agr[8], accr[8];
    #pragma unroll
    for (int o = 0; o < 8; o++) { accr[o] = 0.f; agr[o] = 0.f; }
    float4 pw0, pw1, px0, px1, p3;

    for (int k = 0; k < KKER; k++) {
        for (int net = 0; net < 3; net++) {
            const int IN = (net == 2) ? (SDIM + ADIM) : SDIM;
            const int NCH = IN >> 5;
            const float* W1k = W1s[net] + (size_t)k * HDIM * IN;
            const float* W2k = W2s[net] + (size_t)k * HDIM * HDIM;

            pf_w(W1k, IN, 0, tid, pw0, pw1);
            if (tid < 64) {
                bs[tid]      = __ldg(B1s[net] + k * HDIM + tid);
                bs[64 + tid] = __ldg(B2s[net] + k * HDIM + tid);
            }
            sts_w(wt, tid, pw0, pw1);
            __syncthreads();
            zacc(acc);

            // ---- layer 1: NCH chunks, single-buffer reg-prefetch pipeline ----
            for (int j = 0; j < NCH; j++) {
                bool xanext = false;
                if (j + 1 < NCH) {
                    pf_w(W1k, IN, (j + 1) << 5, tid, pw0, pw1);
                    if (j + 1 >= 8) { pf_xa(actions, b0, (j + 1 - 8) << 5, tid, px0, px1); xanext = true; }
                } else {
                    pf_w(W2k, HDIM, 0, tid, pw0, pw1);
                }
                if (j < 8) mma_chunk(xs, j << 2, wt, acc, wbase, nc0, g, t);
                else       mma_chunk(xa, 0,      wt, acc, wbase, nc0, g, t);
                __syncthreads();
                sts_w(wt, tid, pw0, pw1);
                if (xanext) sts_xa(xa, tid, px0, px1);
                if (j == NCH - 1) { epi_h(acc, h, bs, wbase, nc0, g, t); zacc(acc); }
                __syncthreads();
            }

            // ---- layer 2 (wt = W2c0) ----
            pf_w(W2k, HDIM, 32, tid, pw0, pw1);
            if (tid < 128) {   // prefetch W3 tile
                int o = tid >> 4, c4 = tid & 15;
                if (net == 0)
                    p3 = (o == 0) ? __ldg(reinterpret_cast<const float4*>(kW3 + (size_t)k * HDIM + (c4 << 2)))
                                  : make_float4(0.f, 0.f, 0.f, 0.f);
                else
                    p3 = __ldg(reinterpret_cast<const float4*>(
                             ((net == 1) ? aW3 : cW3) + (size_t)k * 8 * HDIM + o * HDIM + (c4 << 2)));
            }
            mma_chunk(h, 0, wt, acc, wbase, nc0, g, t);
            __syncthreads();
            sts_w(wt, tid, pw0, pw1);
            if (tid < 128) {
                int o = tid >> 4, c4 = tid & 15;
                float* d = w3t + (c4 >> 1) * 66 + o * 8 + (c4 & 1);
                d[0] = tf32f(p3.x); d[2] = tf32f(p3.y); d[4] = tf32f(p3.z); d[6] = tf32f(p3.w);
            }
            __syncthreads();
            mma_chunk(h, 4, wt, acc, wbase, nc0, g, t);
            asm volatile("bar.sync %0, %1;" :: "r"(rg + 1), "r"(64) : "memory");
            epi_h(acc, h, bs + 64, wbase, nc0, g, t);
            zacc(acc);
            asm volatile("bar.sync %0, %1;" :: "r"(rg + 1), "r"(64) : "memory");

            // ---- layer 3 (m16 x n8, nh==0 warps) ----
            if (nh == 0) {
                float a3[4] = {0.f, 0.f, 0.f, 0.f};
                #pragma unroll
                for (int s = 0; s < 8; s++) {
                    const float* ap = h + s * CGS + (wbase + g) * 8 + 2 * t;
                    float2 fa = *reinterpret_cast<const float2*>(ap);
                    float2 fb = *reinterpret_cast<const float2*>(ap + 64);
                    const float* bp = w3t + s * 66 + g * 8 + 2 * t;
                    float2 b = *reinterpret_cast<const float2*>(bp);
                    mma8(a3, fa.x, fb.x, fa.y, fb.y, b.x, b.y);
                }
                int r0 = wbase + g;
                *reinterpret_cast<float2*>(ob + r0 * 8 + 2 * t)       = make_float2(a3[0], a3[1]);
                *reinterpret_cast<float2*>(ob + (r0 + 8) * 8 + 2 * t) = make_float2(a3[2], a3[3]);
            }
            __syncthreads();
            if (tid < 64) {
                const float* orow = ob + tid * 8;
                if (net == 0) {
                    keyr = fabsf(orow[0] + __ldg(kb3 + k)) + 1e-10f;
                } else if (net == 1) {
                    #pragma unroll
                    for (int o = 0; o < 8; o++)
                        agr[o] = sigf(orow[o] + __ldg(ab3 + k * 8 + o));
                } else {
                    #pragma unroll
                    for (int o = 0; o < 8; o++)
                        accr[o] += keyr * agr[o] * sigf(orow[o] + __ldg(cb3 + k * 8 + o));
                }
            }
        }
    }

    if (tid < 64) {
        float4* op = reinterpret_cast<float4*>(out + (size_t)(b0 + tid) * 8);
        op[0] = make_float4(accr[0], accr[1], accr[2], accr[3]);
        op[1] = make_float4(accr[4], accr[5], accr[6], accr[7]);
    }
}

extern "C" void kernel_launch(void* const* d_in, const int* in_sizes, int n_in,
                              void* d_out, int out_size)
{
    const float* states  = (const float*)d_in[0];
    const float* actions = (const float*)d_in[1];
    const float* kW1 = (const float*)d_in[2];  const float* kb1 = (const float*)d_in[3];
    const float* kW2 = (const float*)d_in[4];  const float* kb2 = (const float*)d_in[5];
    const float* kW3 = (const float*)d_in[6];  const float* kb3 = (const float*)d_in[7];
    const float* aW1 = (const float*)d_in[8];  const float* ab1 = (const float*)d_in[9];
    const float* aW2 = (const float*)d_in[10]; const float* ab2 = (const float*)d_in[11];
    const float* aW3 = (const float*)d_in[12]; const float* ab3 = (const float*)d_in[13];
    const float* cW1 = (const float*)d_in[14]; const float* cb1 = (const float*)d_in[15];
    const float* cW2 = (const float*)d_in[16]; const float* cb2 = (const float*)d_in[17];
    const float* cW3 = (const float*)d_in[18]; const float* cb3 = (const float*)d_in[19];
    float* out = (float*)d_out;

    const size_t smem = SMEMF * sizeof(float);   // 103360 B
    cudaFuncSetAttribute(qplex_mma4_kernel,
                         cudaFuncAttributeMaxDynamicSharedMemorySize, (int)smem);
    qplex_mma4_kernel<<<65536 / TB, NT, smem>>>(
        states, actions, kW1, kb1, kW2, kb2, kW3, kb3,
        aW1, ab1, aW2, ab2, aW3, ab3, cW1, cb1, cW2, cb2, cW3, cb3, out);
}

// round 10
// speedup vs baseline: 1.6368x; 1.0407x over previous
#include <cuda_runtime.h>
#include <cstdint>
#include <math.h>

#define SDIM 256
#define ADIM 128
#define HDIM 64
#define KKER 10
#define TB   64
#define NT   128
#define CGS  514

#define XA_O  0u       // 4 cg x 514
#define WT_O  2056u    // 4 cg x 514
#define H_O   4112u    // 8 cg x 514
#define W3_O  8224u    // 8 x 66
#define B_O   8752u    // 128
#define OB_O  8880u    // 64 x 10 (even stride -> float2-aligned)
#define SMEMF 9520u    // *4 = 38080 B -> 4 CTAs/SM

__device__ __forceinline__ uint32_t tf32b(float x) {
    uint32_t u; asm("cvt.rna.tf32.f32 %0, %1;" : "=r"(u) : "f"(x)); return u;
}
__device__ __forceinline__ float tf32f(float x) { return __uint_as_float(tf32b(x)); }
__device__ __forceinline__ float sigf(float x) { return 1.0f / (1.0f + __expf(-x)); }

__device__ __forceinline__ void mma8(float c[4], float a0, float a1, float a2, float a3,
                                     float b0, float b1) {
    asm volatile("mma.sync.aligned.m16n8k8.row.col.f32.tf32.tf32.f32 "
                 "{%0,%1,%2,%3}, {%4,%5,%6,%7}, {%8,%9}, {%0,%1,%2,%3};"
                 : "+f"(c[0]), "+f"(c[1]), "+f"(c[2]), "+f"(c[3])
                 : "r"(__float_as_uint(a0)), "r"(__float_as_uint(a1)),
                   "r"(__float_as_uint(a2)), "r"(__float_as_uint(a3)),
                   "r"(__float_as_uint(b0)), "r"(__float_as_uint(b1)));
}

// prefetch a [64 x 32] tile (rows x k) into 4 float4 regs
__device__ __forceinline__ void pf_t(const float* __restrict__ base, int stride, int c0,
                                     int tid, float4 v[4]) {
    #pragma unroll
    for (int q = 0; q < 4; q++) {
        int idx = tid + NT * q;
        v[q] = __ldg(reinterpret_cast<const float4*>(
                   base + (size_t)(idx >> 3) * stride + c0 + ((idx & 7) << 2)));
    }
}
// store into tiled interleaved layout [4cg][64*8], conflict-free
__device__ __forceinline__ void sts_t(float* __restrict__ dst, int tid, const float4 v[4]) {
    #pragma unroll
    for (int q = 0; q < 4; q++) {
        int idx = tid + NT * q, r = idx >> 3, j = idx & 7;
        float* d = dst + (j >> 1) * CGS + r * 8 + (j & 1);
        d[0] = tf32f(v[q].x); d[2] = tf32f(v[q].y);
        d[4] = tf32f(v[q].z); d[6] = tf32f(v[q].w);
    }
}

// warp m32 x n32 over one 32-k chunk
__device__ __forceinline__ void mma_chunk(const float* __restrict__ A, int cg0,
                                          const float* __restrict__ wtb,
                                          float acc[2][4][4], int wbase, int nc0, int g, int t) {
    #pragma unroll
    for (int s = 0; s < 4; s++) {
        const float* ap = A + (cg0 + s) * CGS + (wbase + g) * 8 + 2 * t;
        float2 a00 = *reinterpret_cast<const float2*>(ap);
        float2 a01 = *reinterpret_cast<const float2*>(ap + 64);
        float2 a10 = *reinterpret_cast<const float2*>(ap + 128);
        float2 a11 = *reinterpret_cast<const float2*>(ap + 192);
        #pragma unroll
        for (int nt = 0; nt < 4; nt++) {
            const float* bp = wtb + s * CGS + (nc0 + nt * 8 + g) * 8 + 2 * t;
            float2 b = *reinterpret_cast<const float2*>(bp);
            mma8(acc[0][nt], a00.x, a01.x, a00.y, a01.y, b.x, b.y);
            mma8(acc[1][nt], a10.x, a11.x, a10.y, a11.y, b.x, b.y);
        }
    }
}
__device__ __forceinline__ void zacc(float acc[2][4][4]) {
    #pragma unroll
    for (int m = 0; m < 2; m++)
        #pragma unroll
        for (int n = 0; n < 4; n++)
            #pragma unroll
            for (int i = 0; i < 4; i++) acc[m][n][i] = 0.0f;
}
__device__ __forceinline__ void epi_h(const float acc[2][4][4], float* __restrict__ h,
                                      const float* __restrict__ bias,
                                      int wbase, int nc0, int g, int t) {
    int cc0 = 2 * t, cc1 = 2 * t + 1;
    int p0 = ((cc0 & 3) << 1) | ((cc0 >> 2) & 1);
    int p1 = ((cc1 & 3) << 1) | ((cc1 >> 2) & 1);
    #pragma unroll
    for (int mt = 0; mt < 2; mt++) {
        int r0 = wbase + 16 * mt + g;
        #pragma unroll
        for (int nt = 0; nt < 4; nt++) {
            int ng = (nc0 >> 3) + nt;
            float b0 = bias[ng * 8 + cc0], b1 = bias[ng * 8 + cc1];
            float* hp = h + ng * CGS + r0 * 8;
            hp[p0]      = tf32f(fmaxf(acc[mt][nt][0] + b0, 0.f));
            hp[p1]      = tf32f(fmaxf(acc[mt][nt][1] + b1, 0.f));
            hp[64 + p0] = tf32f(fmaxf(acc[mt][nt][2] + b0, 0.f));
            hp[64 + p1] = tf32f(fmaxf(acc[mt][nt][3] + b1, 0.f));
        }
    }
}

__global__ void __launch_bounds__(NT, 4)
qplex_mma6_kernel(
    const float* __restrict__ states, const float* __restrict__ actions,
    const float* __restrict__ kW1, const float* __restrict__ kb1,
    const float* __restrict__ kW2, const float* __restrict__ kb2,
    const float* __restrict__ kW3, const float* __restrict__ kb3,
    const float* __restrict__ aW1, const float* __restrict__ ab1,
    const float* __restrict__ aW2, const float* __restrict__ ab2,
    const float* __restrict__ aW3, const float* __restrict__ ab3,
    const float* __restrict__ cW1, const float* __restrict__ cb1,
    const float* __restrict__ cW2, const float* __restrict__ cb2,
    const float* __restrict__ cW3, const float* __restrict__ cb3,
    float* __restrict__ out)
{
    extern __shared__ float sm[];
    float* xa = sm + XA_O;   float* wt = sm + WT_O;  float* h  = sm + H_O;
    float* w3t = sm + W3_O;  float* bs = sm + B_O;   float* ob = sm + OB_O;

    const int tid = threadIdx.x, lane = tid & 31;
    const int g = lane >> 2, t = lane & 3;
    const int wid = tid >> 5, rg = wid >> 1, nh = wid & 1;
    const int wbase = rg << 5, nc0 = nh << 5;
    const int b0 = blockIdx.x * TB;
    const float* sbase = states + (size_t)b0 * SDIM;
    const float* abase = actions + (size_t)b0 * ADIM;

    const float* W1s[3] = {kW1, aW1, cW1};
    const float* B1s[3] = {kb1, ab1, cb1};
    const float* W2s[3] = {kW2, aW2, cW2};
    const float* B2s[3] = {kb2, ab2, cb2};

    float acc[2][4][4], keyr = 0.f, agr[8], accr[8];
    #pragma unroll
    for (int o = 0; o < 8; o++) { accr[o] = 0.f; agr[o] = 0.f; }
    float4 pw[4], px[4], p3;

    for (int k = 0; k < KKER; k++) {
        for (int net = 0; net < 3; net++) {
            const int IN = (net == 2) ? (SDIM + ADIM) : SDIM;
            const int NCH = IN >> 5;
            const float* W1k = W1s[net] + (size_t)k * HDIM * IN;
            const float* W2k = W2s[net] + (size_t)k * HDIM * HDIM;

            pf_t(W1k, IN, 0, tid, pw);
            pf_t(sbase, SDIM, 0, tid, px);
            if (tid < 64) {
                bs[tid]      = __ldg(B1s[net] + k * HDIM + tid);
                bs[64 + tid] = __ldg(B2s[net] + k * HDIM + tid);
            }
            sts_t(wt, tid, pw);
            sts_t(xa, tid, px);
            __syncthreads();
            zacc(acc);

            // ---- layer 1 ----
            for (int j = 0; j < NCH; j++) {
                const bool last = (j == NCH - 1);
                if (!last) {
                    pf_t(W1k, IN, (j + 1) << 5, tid, pw);
                    if (net == 2 && j + 1 >= 8)
                        pf_t(abase, ADIM, (j - 7) << 5, tid, px);
                    else
                        pf_t(sbase, SDIM, (j + 1) << 5, tid, px);
                } else {
                    pf_t(W2k, HDIM, 0, tid, pw);
                }
                mma_chunk(xa, 0, wt, acc, wbase, nc0, g, t);
                __syncthreads();
                sts_t(wt, tid, pw);
                if (!last) sts_t(xa, tid, px);
                else { epi_h(acc, h, bs, wbase, nc0, g, t); zacc(acc); }
                __syncthreads();
            }

            // ---- layer 2 ----
            pf_t(W2k, HDIM, 32, tid, pw);
            {
                int o = tid >> 4, c4 = tid & 15;
                if (net == 0)
                    p3 = (o == 0) ? __ldg(reinterpret_cast<const float4*>(
                                        kW3 + (size_t)k * HDIM + (c4 << 2)))
                                  : make_float4(0.f, 0.f, 0.f, 0.f);
                else
                    p3 = __ldg(reinterpret_cast<const float4*>(
                             ((net == 1) ? aW3 : cW3) + (size_t)k * 8 * HDIM + o * HDIM + (c4 << 2)));
            }
            mma_chunk(h, 0, wt, acc, wbase, nc0, g, t);
            __syncthreads();
            sts_t(wt, tid, pw);
            {
                int o = tid >> 4, c4 = tid & 15;
                float* d = w3t + (c4 >> 1) * 66 + o * 8 + (c4 & 1);
                d[0] = tf32f(p3.x); d[2] = tf32f(p3.y); d[4] = tf32f(p3.z); d[6] = tf32f(p3.w);
            }
            __syncthreads();
            mma_chunk(h, 4, wt, acc, wbase, nc0, g, t);
            asm volatile("bar.sync %0, %1;" :: "r"(rg + 1), "r"(64) : "memory");
            epi_h(acc, h, bs + 64, wbase, nc0, g, t);
            asm volatile("bar.sync %0, %1;" :: "r"(rg + 1), "r"(64) : "memory");

            // ---- layer 3 (m32 x n8, nh==0 warps) ----
            if (nh == 0) {
                float a3[2][4];
                #pragma unroll
                for (int m = 0; m < 2; m++)
                    #pragma unroll
                    for (int i = 0; i < 4; i++) a3[m][i] = 0.f;
                #pragma unroll
                for (int s = 0; s < 8; s++) {
                    const float* ap = h + s * CGS + (wbase + g) * 8 + 2 * t;
                    float2 a00 = *reinterpret_cast<const float2*>(ap);
                    float2 a01 = *reinterpret_cast<const float2*>(ap + 64);
                    float2 a10 = *reinterpret_cast<const float2*>(ap + 128);
                    float2 a11 = *reinterpret_cast<const float2*>(ap + 192);
                    const float* bp = w3t + s * 66 + g * 8 + 2 * t;
                    float2 b = *reinterpret_cast<const float2*>(bp);
                    mma8(a3[0], a00.x, a01.x, a00.y, a01.y, b.x, b.y);
                    mma8(a3[1], a10.x, a11.x, a10.y, a11.y, b.x, b.y);
                }
                #pragma unroll
                for (int mt = 0; mt < 2; mt++) {
                    int r0 = wbase + 16 * mt + g;
                    *reinterpret_cast<float2*>(ob + r0 * 10 + 2 * t)       = make_float2(a3[mt][0], a3[mt][1]);
                    *reinterpret_cast<float2*>(ob + (r0 + 8) * 10 + 2 * t) = make_float2(a3[mt][2], a3[mt][3]);
                }
            }
            __syncthreads();
            if (tid < 64) {
                const float* orow = ob + tid * 10;
                if (net == 0) {
                    keyr = fabsf(orow[0] + __ldg(kb3 + k)) + 1e-10f;
                } else if (net == 1) {
                    #pragma unroll
                    for (int o = 0; o < 8; o++)
                        agr[o] = sigf(orow[o] + __ldg(ab3 + k * 8 + o));
                } else {
                    #pragma unroll
                    for (int o = 0; o < 8; o++)
                        accr[o] += keyr * agr[o] * sigf(orow[o] + __ldg(cb3 + k * 8 + o));
                }
            }
        }
    }

    if (tid < 64) {
        float4* op = reinterpret_cast<float4*>(out + (size_t)(b0 + tid) * 8);
        op[0] = make_float4(accr[0], accr[1], accr[2], accr[3]);
        op[1] = make_float4(accr[4], accr[5], accr[6], accr[7]);
    }
}

extern "C" void kernel_launch(void* const* d_in, const int* in_sizes, int n_in,
                              void* d_out, int out_size)
{
    const float* states  = (const float*)d_in[0];
    const float* actions = (const float*)d_in[1];
    const float* kW1 = (const float*)d_in[2];  const float* kb1 = (const float*)d_in[3];
    const float* kW2 = (const float*)d_in[4];  const float* kb2 = (const float*)d_in[5];
    const float* kW3 = (const float*)d_in[6];  const float* kb3 = (const float*)d_in[7];
    const float* aW1 = (const float*)d_in[8];  const float* ab1 = (const float*)d_in[9];
    const float* aW2 = (const float*)d_in[10]; const float* ab2 = (const float*)d_in[11];
    const float* aW3 = (const float*)d_in[12]; const float* ab3 = (const float*)d_in[13];
    const float* cW1 = (const float*)d_in[14]; const float* cb1 = (const float*)d_in[15];
    const float* cW2 = (const float*)d_in[16]; const float* cb2 = (const float*)d_in[17];
    const float* cW3 = (const float*)d_in[18]; const float* cb3 = (const float*)d_in[19];
    float* out = (float*)d_out;

    const size_t smem = SMEMF * sizeof(float);   // 38080 B
    cudaFuncSetAttribute(qplex_mma6_kernel,
                         cudaFuncAttributeMaxDynamicSharedMemorySize, (int)smem);
    qplex_mma6_kernel<<<65536 / TB, NT, smem>>>(
        states, actions, kW1, kb1, kW2, kb2, kW3, kb3,
        aW1, ab1, aW2, ab2, aW3, ab3, cW1, cb1, cW2, cb2, cW3, cb3, out);
}